// round 1
// baseline (speedup 1.0000x reference)
#include <cuda_runtime.h>
#include <math.h>

#define M_BATCH 2048
#define N_OUT   4096
#define K_IN    4096

// 64 MB scratch for the normalized/masked weight matrix (module-load allocation,
// permitted per pitfalls.md; no runtime alloc).
__device__ float g_Wn[(size_t)N_OUT * K_IN];

// ---------------------------------------------------------------------------
// Prep: one block per output row o.
//   br     = o/32 (block row), nonzero cols i in [0, 32*(br+1))
//   Wm     = exp(W) on the diagonal 32x32 block, W on strictly-lower blocks
//   Wn     = exp(W_log_scale[o]) * Wm / ||Wm||
//   jac    = log of diag block of Wn = wls[o] + W[o,i] - log(norm)   (closed form)
// Also zero-fills g_Wn[o][ncols .. KmaxTile) where KmaxTile = 128*(o/128 + 1),
// the K bound the GEMM uses for this row's 128-row output tile.
// ---------------------------------------------------------------------------
__global__ void prep_kernel(const float* __restrict__ W,
                            const float* __restrict__ wls,
                            float* __restrict__ jac_out) {
    const int o = blockIdx.x;
    const int br = o >> 5;
    const int ncols = (br + 1) << 5;
    const int dstart = br << 5;
    const int kmax_tile = ((o >> 7) + 1) << 7;

    const float* wrow = W + (size_t)o * K_IN;
    float* wnrow = g_Wn + (size_t)o * K_IN;

    float ss = 0.f;
    for (int i = threadIdx.x; i < ncols; i += blockDim.x) {
        float w = wrow[i];
        float wm = (i >= dstart) ? expf(w) : w;
        ss += wm * wm;
    }
    __shared__ float red[256];
    red[threadIdx.x] = ss;
    __syncthreads();
    #pragma unroll
    for (int s = 128; s > 0; s >>= 1) {
        if (threadIdx.x < s) red[threadIdx.x] += red[threadIdx.x + s];
        __syncthreads();
    }
    const float norm   = sqrtf(red[0]);
    const float lscale = wls[o];
    const float coef   = expf(lscale) / norm;
    const float logn   = logf(norm);

    for (int i = threadIdx.x; i < ncols; i += blockDim.x) {
        float w = wrow[i];
        float wm = (i >= dstart) ? expf(w) : w;
        wnrow[i] = coef * wm;
        if (i >= dstart)
            jac_out[(size_t)o * 32 + (i - dstart)] = lscale + w - logn;
    }
    // Zero garbage region the GEMM tile will sweep over for this row.
    for (int i = ncols + threadIdx.x; i < kmax_tile; i += blockDim.x)
        wnrow[i] = 0.f;
}

// ---------------------------------------------------------------------------
// GEMM: y[m, n] = sum_k x[m, k] * Wn[n, k] + bias[n]
// 128x128 block tile, BK=16, 256 threads, 8x8 per thread.
// Triangular structure: out-tile n covers block rows [4n, 4n+3] ->
// K loop bound Kmax = 128*(n_tile+1).
// ---------------------------------------------------------------------------
#define BM 128
#define BN 128
#define BK 16
#define TM 8
#define TN 8

__global__ __launch_bounds__(256, 2)
void gemm_kernel(const float* __restrict__ x,
                 const float* __restrict__ bias,
                 float* __restrict__ y) {
    __shared__ float As[BK][BM];   // transposed: As[k][m]
    __shared__ float Bs[BK][BN];   // transposed: Bs[k][n]

    const int n0 = blockIdx.x * BN;
    const int m0 = blockIdx.y * BM;
    const int Kmax = (blockIdx.x + 1) * BN;   // = 128*(n_tile+1)

    const int tid = threadIdx.x;
    const int tr = tid >> 4;     // 0..15 (rows of thread grid)
    const int tc = tid & 15;     // 0..15 (cols)

    const int lk = tid & 3;      // float4 index along K
    const int lm = tid >> 2;     // 0..63

    float acc[TM][TN];
    #pragma unroll
    for (int i = 0; i < TM; i++)
        #pragma unroll
        for (int j = 0; j < TN; j++) acc[i][j] = 0.f;

    const float* Abase = x    + (size_t)m0 * K_IN;
    const float* Bbase = g_Wn + (size_t)n0 * K_IN;

    for (int k0 = 0; k0 < Kmax; k0 += BK) {
        #pragma unroll
        for (int r = 0; r < 2; r++) {
            const int row = lm + r * 64;
            float4 va = *(const float4*)(Abase + (size_t)row * K_IN + k0 + lk * 4);
            As[lk * 4 + 0][row] = va.x;
            As[lk * 4 + 1][row] = va.y;
            As[lk * 4 + 2][row] = va.z;
            As[lk * 4 + 3][row] = va.w;
            float4 vb = *(const float4*)(Bbase + (size_t)row * K_IN + k0 + lk * 4);
            Bs[lk * 4 + 0][row] = vb.x;
            Bs[lk * 4 + 1][row] = vb.y;
            Bs[lk * 4 + 2][row] = vb.z;
            Bs[lk * 4 + 3][row] = vb.w;
        }
        __syncthreads();

        #pragma unroll
        for (int kk = 0; kk < BK; kk++) {
            float a[TM], b[TN];
            #pragma unroll
            for (int i = 0; i < TM; i++) a[i] = As[kk][tr * TM + i];
            #pragma unroll
            for (int j = 0; j < TN; j++) b[j] = Bs[kk][tc * TN + j];
            #pragma unroll
            for (int i = 0; i < TM; i++)
                #pragma unroll
                for (int j = 0; j < TN; j++)
                    acc[i][j] += a[i] * b[j];
        }
        __syncthreads();
    }

    #pragma unroll
    for (int i = 0; i < TM; i++) {
        const int m = m0 + tr * TM + i;
        float* yrow = y + (size_t)m * N_OUT + n0 + tc * TN;
        #pragma unroll
        for (int j = 0; j < TN; j += 4) {
            float4 v;
            v.x = acc[i][j + 0] + bias[n0 + tc * TN + j + 0];
            v.y = acc[i][j + 1] + bias[n0 + tc * TN + j + 1];
            v.z = acc[i][j + 2] + bias[n0 + tc * TN + j + 2];
            v.w = acc[i][j + 3] + bias[n0 + tc * TN + j + 3];
            *(float4*)(yrow + j) = v;
        }
    }
}

extern "C" void kernel_launch(void* const* d_in, const int* in_sizes, int n_in,
                              void* d_out, int out_size) {
    const float* x    = (const float*)d_in[0];   // [2048, 4096]
    const float* W    = (const float*)d_in[1];   // [4096, 4096]
    const float* bias = (const float*)d_in[2];   // [4096]
    const float* wls  = (const float*)d_in[3];   // [4096, 1]
    // d_in[4], d_in[5]: masks — deterministic, never read.

    float* y   = (float*)d_out;                         // [2048, 4096]
    float* jac = y + (size_t)M_BATCH * N_OUT;           // [128, 32, 32]

    prep_kernel<<<N_OUT, 256>>>(W, wls, jac);
    gemm_kernel<<<dim3(N_OUT / BN, M_BATCH / BM), 256>>>(x, bias, y);
}

// round 3
// speedup vs baseline: 4.6352x; 4.6352x over previous
#include <cuda_runtime.h>
#include <cuda_bf16.h>
#include <math.h>
#include <stdint.h>

#define M_BATCH 2048
#define N_OUT   4096
#define K_IN    4096

// Persistent bf16 hi/lo operands (module-load allocations; no runtime alloc).
__device__ __nv_bfloat16 g_xh[(size_t)M_BATCH * K_IN];
__device__ __nv_bfloat16 g_xl[(size_t)M_BATCH * K_IN];
__device__ __nv_bfloat16 g_wh[(size_t)N_OUT * K_IN];
__device__ __nv_bfloat16 g_wl[(size_t)N_OUT * K_IN];

// ---------------------------------------------------------------------------
// Helpers (non-'a' features only: cp.async, ldmatrix, mma.sync — all compile
// for compute_103)
// ---------------------------------------------------------------------------
__device__ __forceinline__ uint32_t smem_u32(const void* p) {
    uint32_t a;
    asm("{ .reg .u64 t; cvta.to.shared.u64 t, %1; cvt.u32.u64 %0, t; }"
        : "=r"(a) : "l"(p));
    return a;
}
__device__ __forceinline__ void cp16(uint32_t s, const void* g) {
    asm volatile("cp.async.cg.shared.global [%0], [%1], 16;"
                 :: "r"(s), "l"(g));
}
#define CP_COMMIT() asm volatile("cp.async.commit_group;" ::: "memory")
#define CP_WAIT1()  asm volatile("cp.async.wait_group 1;" ::: "memory")
#define CP_WAIT0()  asm volatile("cp.async.wait_group 0;" ::: "memory")

#define LDM4(d, addr)                                                         \
    asm volatile("ldmatrix.sync.aligned.m8n8.x4.shared.b16 {%0,%1,%2,%3}, [%4];" \
        : "=r"((d)[0]), "=r"((d)[1]), "=r"((d)[2]), "=r"((d)[3]) : "r"(addr))

#define MMA16816(c, a, b0, b1)                                                \
    asm volatile("mma.sync.aligned.m16n8k16.row.col.f32.bf16.bf16.f32 "       \
        "{%0,%1,%2,%3}, {%4,%5,%6,%7}, {%8,%9}, {%0,%1,%2,%3};"               \
        : "+f"((c)[0]), "+f"((c)[1]), "+f"((c)[2]), "+f"((c)[3])              \
        : "r"((a)[0]), "r"((a)[1]), "r"((a)[2]), "r"((a)[3]),                 \
          "r"(b0), "r"(b1))

// ---------------------------------------------------------------------------
// Prep x: split fp32 -> bf16 hi + bf16 lo
// ---------------------------------------------------------------------------
__global__ void prep_x(const float* __restrict__ x) {
    size_t i = ((size_t)blockIdx.x * blockDim.x + threadIdx.x) * 4;
    float4 v = *(const float4*)(x + i);
    __nv_bfloat16 h0 = __float2bfloat16(v.x);
    __nv_bfloat16 h1 = __float2bfloat16(v.y);
    __nv_bfloat16 h2 = __float2bfloat16(v.z);
    __nv_bfloat16 h3 = __float2bfloat16(v.w);
    __nv_bfloat16 l0 = __float2bfloat16(v.x - __bfloat162float(h0));
    __nv_bfloat16 l1 = __float2bfloat16(v.y - __bfloat162float(h1));
    __nv_bfloat16 l2 = __float2bfloat16(v.z - __bfloat162float(h2));
    __nv_bfloat16 l3 = __float2bfloat16(v.w - __bfloat162float(h3));
    *(__nv_bfloat162*)(&g_xh[i])     = __halves2bfloat162(h0, h1);
    *(__nv_bfloat162*)(&g_xh[i + 2]) = __halves2bfloat162(h2, h3);
    *(__nv_bfloat162*)(&g_xl[i])     = __halves2bfloat162(l0, l1);
    *(__nv_bfloat162*)(&g_xl[i + 2]) = __halves2bfloat162(l2, l3);
}

// ---------------------------------------------------------------------------
// Prep W: normalized masked row -> bf16 hi/lo; jac closed form; zero-pad to
// the GEMM tile K bound.
// ---------------------------------------------------------------------------
__global__ void prep_w(const float* __restrict__ W,
                       const float* __restrict__ wls,
                       float* __restrict__ jac_out) {
    const int o = blockIdx.x;
    const int br = o >> 5;
    const int ncols = (br + 1) << 5;
    const int dstart = br << 5;
    const int kmax_tile = ((o >> 7) + 1) << 7;

    const float* wrow = W + (size_t)o * K_IN;
    __nv_bfloat16* wh = g_wh + (size_t)o * K_IN;
    __nv_bfloat16* wl = g_wl + (size_t)o * K_IN;

    float ss = 0.f;
    for (int i = threadIdx.x; i < ncols; i += blockDim.x) {
        float w = wrow[i];
        float wm = (i >= dstart) ? expf(w) : w;
        ss += wm * wm;
    }
    __shared__ float red[256];
    red[threadIdx.x] = ss;
    __syncthreads();
    #pragma unroll
    for (int s = 128; s > 0; s >>= 1) {
        if (threadIdx.x < s) red[threadIdx.x] += red[threadIdx.x + s];
        __syncthreads();
    }
    const float norm   = sqrtf(red[0]);
    const float lscale = wls[o];
    const float coef   = expf(lscale) / norm;
    const float logn   = logf(norm);

    for (int i = threadIdx.x; i < ncols; i += blockDim.x) {
        float w = wrow[i];
        float wm = (i >= dstart) ? expf(w) : w;
        float wn = coef * wm;
        __nv_bfloat16 h = __float2bfloat16(wn);
        wh[i] = h;
        wl[i] = __float2bfloat16(wn - __bfloat162float(h));
        if (i >= dstart)
            jac_out[(size_t)o * 32 + (i - dstart)] = lscale + w - logn;
    }
    const __nv_bfloat16 z = __float2bfloat16(0.f);
    for (int i = ncols + threadIdx.x; i < kmax_tile; i += blockDim.x) {
        wh[i] = z;
        wl[i] = z;
    }
}

// ---------------------------------------------------------------------------
// mma.sync bf16 GEMM with 2-term split (3 passes): y = x @ Wn^T + bias.
// CTA tile 128x128, 8 warps (4m x 2n => 32x64 per warp), BK=64,
// double-buffered cp.async, XOR-swizzled smem + ldmatrix.
// Triangular: Kmax = 128*(nt+1); heaviest tiles first.
// Stage layout (64 KB): Ah @0, Al @16K, Bh @32K, Bl @48K; 2 stages = 128 KB.
// Swizzle: 16B-chunk index ^= (row & 7)  (rows are 128 B).
// ---------------------------------------------------------------------------
#define STAGE 65536
#define SMEM_TOTAL (2 * STAGE)

__global__ __launch_bounds__(256, 1)
void gemm_mma(const float* __restrict__ bias, float* __restrict__ y) {
    extern __shared__ __align__(1024) char smem[];
    const uint32_t sb = smem_u32(smem);

    const int tid  = threadIdx.x;
    const int wid  = tid >> 5;
    const int lane = tid & 31;
    const int wm = wid >> 1;          // 0..3
    const int wn = wid & 1;           // 0..1

    const int bid = blockIdx.x;
    const int nt = 31 - (bid >> 4);   // heaviest n-tiles first
    const int mt = bid & 15;
    const int n0 = nt << 7;
    const int m0 = mt << 7;
    const int NC = (nt + 1) << 1;     // K chunks of 64

    const __nv_bfloat16* gAh = g_xh + (size_t)m0 * K_IN;
    const __nv_bfloat16* gAl = g_xl + (size_t)m0 * K_IN;
    const __nv_bfloat16* gBh = g_wh + (size_t)n0 * K_IN;
    const __nv_bfloat16* gBl = g_wl + (size_t)n0 * K_IN;

    float acc[2][8][4];
    #pragma unroll
    for (int i = 0; i < 2; i++)
        #pragma unroll
        for (int j = 0; j < 8; j++)
            #pragma unroll
            for (int k = 0; k < 4; k++) acc[i][j][k] = 0.f;

    // per-thread load coordinates (4 chunks per tile per thread)
    auto load_stage = [&](int s, int k0) {
        const uint32_t base = sb + s * STAGE;
        #pragma unroll
        for (int i = 0; i < 4; i++) {
            const int idx = tid + (i << 8);       // 0..1023
            const int r = idx >> 3;
            const int ch = idx & 7;
            const size_t go = (size_t)r * K_IN + k0 + (ch << 3);
            const uint32_t so = (uint32_t)((r << 7) | ((ch ^ (r & 7)) << 4));
            cp16(base + so,         gAh + go);
            cp16(base + 16384 + so, gAl + go);
            cp16(base + 32768 + so, gBh + go);
            cp16(base + 49152 + so, gBl + go);
        }
    };

    load_stage(0, 0);
    CP_COMMIT();

    for (int c = 0; c < NC; ++c) {
        if (c + 1 < NC) {
            load_stage((c + 1) & 1, (c + 1) << 6);
            CP_COMMIT();
            CP_WAIT1();
        } else {
            CP_WAIT0();
        }
        __syncthreads();

        const uint32_t base = sb + (c & 1) * STAGE;
        #pragma unroll
        for (int ks = 0; ks < 4; ks++) {
            uint32_t ah[2][4], al[2][4];
            #pragma unroll
            for (int mf = 0; mf < 2; mf++) {
                const int row = (wm << 5) + (mf << 4) + (lane & 15);
                const int ch = ((ks << 1) + (lane >> 4)) ^ (row & 7);
                const uint32_t ad = base + (row << 7) + (ch << 4);
                LDM4(ah[mf], ad);
                LDM4(al[mf], ad + 16384);
            }
            #pragma unroll
            for (int ng = 0; ng < 4; ng++) {
                const int n = (wn << 6) + (ng << 4) + ((lane >> 4) << 3) + (lane & 7);
                const int ch = ((ks << 1) + ((lane >> 3) & 1)) ^ (n & 7);
                const uint32_t bd = base + 32768 + (n << 7) + (ch << 4);
                uint32_t bh[4], bl[4];
                LDM4(bh, bd);
                LDM4(bl, bd + 16384);
                #pragma unroll
                for (int mf = 0; mf < 2; mf++) {
                    #pragma unroll
                    for (int h = 0; h < 2; h++) {
                        float* cc = acc[mf][(ng << 1) + h];
                        MMA16816(cc, ah[mf], bh[2 * h], bh[2 * h + 1]);
                        MMA16816(cc, ah[mf], bl[2 * h], bl[2 * h + 1]);
                        MMA16816(cc, al[mf], bh[2 * h], bh[2 * h + 1]);
                    }
                }
            }
        }
        __syncthreads();
    }

    // Epilogue: c-frag thread map: (r = lane>>2, c = 2*(lane&3)); c2,c3 at r+8.
    #pragma unroll
    for (int mf = 0; mf < 2; mf++) {
        const int r = m0 + (wm << 5) + (mf << 4) + (lane >> 2);
        #pragma unroll
        for (int nf = 0; nf < 8; nf++) {
            const int cc = n0 + (wn << 6) + (nf << 3) + ((lane & 3) << 1);
            const float b0 = __ldg(bias + cc);
            const float b1 = __ldg(bias + cc + 1);
            float2 v0 = { acc[mf][nf][0] + b0, acc[mf][nf][1] + b1 };
            float2 v1 = { acc[mf][nf][2] + b0, acc[mf][nf][3] + b1 };
            *(float2*)(y + (size_t)r * N_OUT + cc)       = v0;
            *(float2*)(y + (size_t)(r + 8) * N_OUT + cc) = v1;
        }
    }
}

// ---------------------------------------------------------------------------
extern "C" void kernel_launch(void* const* d_in, const int* in_sizes, int n_in,
                              void* d_out, int out_size) {
    const float* x    = (const float*)d_in[0];   // [2048, 4096]
    const float* W    = (const float*)d_in[1];   // [4096, 4096]
    const float* bias = (const float*)d_in[2];   // [4096]
    const float* wls  = (const float*)d_in[3];   // [4096, 1]
    // masks (d_in[4], d_in[5]) are deterministic; never read.

    float* y   = (float*)d_out;                        // [2048, 4096]
    float* jac = y + (size_t)M_BATCH * N_OUT;          // [128, 32, 32]

    cudaFuncSetAttribute(gemm_mma, cudaFuncAttributeMaxDynamicSharedMemorySize,
                         SMEM_TOTAL);

    prep_x<<<(M_BATCH * K_IN) / (256 * 4), 256>>>(x);
    prep_w<<<N_OUT, 256>>>(W, wls, jac);
    gemm_mma<<<512, 256, SMEM_TOTAL>>>(bias, y);
}